// round 10
// baseline (speedup 1.0000x reference)
#include <cuda_runtime.h>
#include <cstdint>

#define B_SZ    16
#define IN_F    8192
#define OUT_F   8192
#define GRP     128
#define NGRP    64
#define CHUNK   512            // x columns per chunk
#define THREADS 512
#define RPT     32             // rows per tile
#define TILES   2              // persistent row-tiles per block (64 rows total)
#define WST     6              // W ring stages
#define XST     2
#define NGI     128            // total group-iterations (2 tiles x 64)

#define WS_STAGE_F  (RPT * GRP)        // 4096 floats (16 KB) per W stage
#define XR_STAGE_F  (B_SZ * CHUNK)     // 8192 floats (32 KB) per x stage
#define WS_OFF      128
#define XR_OFF      (WS_OFF + WST * WS_STAGE_F * 4)   // 98432
#define SC_OFF      (XR_OFF + XST * XR_STAGE_F * 4)   // 163968
#define SMEM_TOTAL  (SC_OFF + 64 * NGRP * 4)          // 180352

typedef unsigned long long ull;

__device__ __forceinline__ ull pack2(float v) {
    ull r; asm("mov.b64 %0, {%1, %1};" : "=l"(r) : "f"(v)); return r;
}
__device__ __forceinline__ ull mul2(ull a, ull b) {
    ull r; asm("mul.rn.f32x2 %0, %1, %2;" : "=l"(r) : "l"(a), "l"(b)); return r;
}
__device__ __forceinline__ void fma2(ull& d, ull a, ull b) {
    asm("fma.rn.f32x2 %0, %1, %2, %0;" : "+l"(d) : "l"(a), "l"(b));
}
__device__ __forceinline__ ull add2(ull a, ull b) {
    ull r; asm("add.rn.f32x2 %0, %1, %2;" : "=l"(r) : "l"(a), "l"(b)); return r;
}
__device__ __forceinline__ void unpack2(ull v, float& lo, float& hi) {
    asm("mov.b64 {%0, %1}, %2;" : "=f"(lo), "=f"(hi) : "l"(v));
}
__device__ __forceinline__ void cp_async16(uint32_t dst, const float* src) {
    asm volatile("cp.async.cg.shared.global [%0], [%1], 16;" :: "r"(dst), "l"(src));
}
__device__ __forceinline__ void mbar_init(uint32_t a, uint32_t cnt) {
    asm volatile("mbarrier.init.shared.b64 [%0], %1;" :: "r"(a), "r"(cnt) : "memory");
}
__device__ __forceinline__ void mbar_arrive(uint32_t a) {
    asm volatile("mbarrier.arrive.release.cta.shared::cta.b64 _, [%0];" :: "r"(a) : "memory");
}
__device__ __forceinline__ void cpasync_mbar_arrive_noinc(uint32_t a) {
    asm volatile("cp.async.mbarrier.arrive.noinc.shared::cta.b64 [%0];" :: "r"(a) : "memory");
}
__device__ __forceinline__ void mbar_wait(uint32_t a, uint32_t parity) {
    asm volatile(
        "{\n\t.reg .pred P;\n\t"
        "WL_%=:\n\t"
        "mbarrier.try_wait.parity.acquire.cta.shared::cta.b64 P, [%0], %1, 0x989680;\n\t"
        "@P bra.uni WD_%=;\n\t"
        "bra.uni WL_%=;\n\t"
        "WD_%=:\n\t}"
        :: "r"(a), "r"(parity) : "memory");
}

__global__ void __launch_bounds__(THREADS, 1)
axcore_linear_kernel(const float* __restrict__ x,
                     const float* __restrict__ W,
                     const float* __restrict__ scale,
                     const float* __restrict__ bias,
                     float* __restrict__ out)
{
    extern __shared__ char smem[];
    float* ws = reinterpret_cast<float*>(smem + WS_OFF);
    float* xr = reinterpret_cast<float*>(smem + XR_OFF);
    float* sc = reinterpret_cast<float*>(smem + SC_OFF);
    const uint32_t smem_u32 = (uint32_t)__cvta_generic_to_shared(smem);
#define FULLW(s)  (smem_u32 + (s) * 8)
#define EMPTYW(s) (smem_u32 + 48 + (s) * 8)
#define FULLX(s)  (smem_u32 + 96 + (s) * 8)

    const int tid  = threadIdx.x;
    const int lane = tid & 31;
    const int warp = tid >> 5;
    const int rg   = warp >> 2;      // row subgroup (0..3): rows rg*8..rg*8+7
    const int bg   = warp & 3;       // batch subgroup: batches bg*4..bg*4+3
    const int row0 = blockIdx.x * (RPT * TILES);
    const bool prod = (warp < 4);    // producer warps (tid < 128)

    if (tid == 0) {
#pragma unroll
        for (int s = 0; s < WST; s++) {
            mbar_init(FULLW(s), 128);    // noinc cp.async arrivals
            mbar_init(EMPTYW(s), 16);    // elected per-warp arrives
        }
#pragma unroll
        for (int s = 0; s < XST; s++) mbar_init(FULLX(s), 128);
    }
    __syncthreads();

    // ---- W group-iter gi -> ring slot: 32 rows x 128 cols (producers)
#define ISSUE_W(gi, slot) do {                                                \
        const float* _src = W + (size_t)(row0 + ((gi) >> 6) * RPT) * IN_F     \
                              + ((gi) & 63) * GRP;                            \
        const uint32_t _db = smem_u32 + WS_OFF + (slot) * (WS_STAGE_F * 4);   \
        _Pragma("unroll")                                                     \
        for (int j = 0; j < 8; j++) {                                         \
            const int i = tid + 128 * j;        /* 0..1023 */                 \
            const int r = i >> 5, cf = i & 31;  /* 32 rows x 32 x 16B */      \
            cp_async16(_db + (uint32_t)(r * GRP + cf * 4) * 4,                \
                       _src + (size_t)r * IN_F + cf * 4);                     \
        }                                                                     \
        cpasync_mbar_arrive_noinc(FULLW(slot));                               \
    } while (0)

    // ---- x chunk instance cn -> stage [16][512], straight rows (producers)
#define ISSUE_X(cn, slot) do {                                                \
        const float* _src = x + ((cn) & 15) * CHUNK;                          \
        const uint32_t _db = smem_u32 + XR_OFF + (slot) * (XR_STAGE_F * 4);   \
        _Pragma("unroll")                                                     \
        for (int j = 0; j < 16; j++) {                                        \
            const int i = tid + 128 * j;          /* 0..2047 */               \
            const int b = i >> 7, cf = i & 127;   /* 16 rows x 128 x 16B */   \
            cp_async16(_db + (uint32_t)(b * CHUNK + cf * 4) * 4,              \
                       _src + (size_t)b * IN_F + cf * 4);                     \
        }                                                                     \
        cpasync_mbar_arrive_noinc(FULLX(slot));                               \
    } while (0)

    // ---- prologue: W gi=0..4 (5 ahead), x instance 0; stage scales
    if (prod) {
        ISSUE_W(0, 0); ISSUE_W(1, 1); ISSUE_W(2, 2); ISSUE_W(3, 3); ISSUE_W(4, 4);
        ISSUE_X(0, 0);
    }
    for (int idx = tid; idx < 64 * NGRP; idx += THREADS)
        sc[idx] = scale[(size_t)(row0 + (idx >> 6)) * NGRP + (idx & 63)];
    __syncthreads();   // sc visible

    // acc[r][b]: f32x2 over (even col, odd col) partial sums
    ull acc[8][4];
#pragma unroll
    for (int r = 0; r < 8; r++)
#pragma unroll
        for (int b = 0; b < 4; b++) acc[r][b] = 0ull;

    int cwsl = 0, cwph = 0;        // consumer W cursor
    int pwsl = WST - 1, pwph = 0;  // producer W cursor (issues gi+5)
    int cxsl = 0, cxph = 0;        // consumer x cursor

    for (int t = 0; t < TILES; t++) {
        for (int g = 0; g < NGRP; g++) {
            const int gi = t * NGRP + g;
            if (prod && gi + 5 < NGI) {
                mbar_wait(EMPTYW(pwsl), pwph ^ 1);
                ISSUE_W(gi + 5, pwsl);
                // EMPTY drain => consumers done gi-1 => past start of chunk
                // gi>>2 => chunk (gi>>2)-1 fully read => slot (cn+1)&1 free.
                if ((gi & 3) == 1) {
                    const int cn = (gi >> 2) + 1;
                    if (cn < NGI / 4) ISSUE_X(cn, cn & 1);
                }
                if (++pwsl == WST) { pwsl = 0; pwph ^= 1; }
            }
            mbar_wait(FULLW(cwsl), cwph);
            if ((g & 3) == 0) mbar_wait(FULLX(cxsl), cxph);

            const float* wst = ws + cwsl * WS_STAGE_F + (rg * 8) * GRP;
            const float* xb  = xr + cxsl * XR_STAGE_F + (bg * 4) * CHUNK
                                  + (g & 3) * GRP;
            float s[8];
#pragma unroll
            for (int r = 0; r < 8; r++)
                s[r] = sc[(t * RPT + rg * 8 + r) * NGRP + g];

#pragma unroll
            for (int k = 0; k < 2; k++) {
                const int c2 = 2 * lane + 64 * k;
                ull x2[4];
#pragma unroll
                for (int b = 0; b < 4; b++)
                    x2[b] = *reinterpret_cast<const ull*>(xb + b * CHUNK + c2);
#pragma unroll
                for (int r = 0; r < 8; r++) {
                    const ull w2 =
                        *reinterpret_cast<const ull*>(wst + r * GRP + c2);
                    const ull ws2 = mul2(w2, pack2(s[r]));
#pragma unroll
                    for (int b = 0; b < 4; b++) fma2(acc[r][b], ws2, x2[b]);
                }
            }

            if (lane == 0) mbar_arrive(EMPTYW(cwsl));
            if (++cwsl == WST) { cwsl = 0; cwph ^= 1; }
            if ((g & 3) == 3) { if (++cxsl == XST) { cxsl = 0; cxph ^= 1; } }
        }

        // ---- tile writeback: butterfly over lanes, fold col halves
#pragma unroll
        for (int r = 0; r < 8; r++)
#pragma unroll
            for (int b = 0; b < 4; b++) {
                ull v = acc[r][b];
#pragma unroll
                for (int off = 16; off > 0; off >>= 1)
                    v = add2(v, __shfl_xor_sync(0xffffffffu, v, off));
                if (lane == r * 4 + b) {
                    const int row = row0 + t * RPT + rg * 8 + r;
                    float lo, hi;
                    unpack2(v, lo, hi);
                    out[(size_t)(bg * 4 + b) * OUT_F + row] =
                        lo + hi + __ldg(bias + row);
                }
                acc[r][b] = 0ull;   // reset for next tile
            }
    }
}

extern "C" void kernel_launch(void* const* d_in, const int* in_sizes, int n_in,
                              void* d_out, int out_size)
{
    const float* x     = (const float*)d_in[0]; // [16, 8192]
    const float* W     = (const float*)d_in[1]; // [8192, 8192]
    const float* scale = (const float*)d_in[2]; // [8192, 64]
    const float* bias  = (const float*)d_in[3]; // [1, 8192]
    // d_in[4] = types — constant lookup in reference; no float math: unused
    float* out = (float*)d_out;                 // [16, 8192]

    cudaFuncSetAttribute(axcore_linear_kernel,
                         cudaFuncAttributeMaxDynamicSharedMemorySize, SMEM_TOTAL);

    dim3 grid(OUT_F / (RPT * TILES)); // 128
    dim3 block(THREADS);              // 512
    axcore_linear_kernel<<<grid, block, SMEM_TOTAL>>>(x, W, scale, bias, out);
}

// round 12
// speedup vs baseline: 1.1528x; 1.1528x over previous
#include <cuda_runtime.h>
#include <cstdint>

#define B_SZ    16
#define IN_F    8192
#define OUT_F   8192
#define GRP     128
#define NGRP    64
#define XCH     256            // x cols per chunk (2 groups)
#define NXCH    32
#define THREADS 576            // 16 consumer warps + 2 producer warps
#define RPB     64
#define WST     4              // W ring stages
#define XST     3              // x ring stages
#define XPAD    20             // 80B col stride -> conflict-free LDS.128

#define WS_STAGE_F  (RPB * GRP)        // 8192 floats (32 KB) per W stage
#define XR_STAGE_F  (XCH * XPAD)       // 5120 floats (20 KB) per x stage
#define WS_OFF      1024
#define XR_OFF      (WS_OFF + WST * WS_STAGE_F * 4)   // 132096
#define SC_OFF      (XR_OFF + XST * XR_STAGE_F * 4)   // 193536
#define SMEM_TOTAL  (SC_OFF + RPB * NGRP * 4)         // 209920

typedef unsigned long long ull;

__device__ float g_xT[IN_F * B_SZ];    // pre-transposed x [8192][16]

__device__ __forceinline__ ull pack2(float v) {
    ull r; asm("mov.b64 %0, {%1, %1};" : "=l"(r) : "f"(v)); return r;
}
__device__ __forceinline__ void fma2(ull& d, ull a, ull b) {
    asm("fma.rn.f32x2 %0, %1, %2, %0;" : "+l"(d) : "l"(a), "l"(b));
}
__device__ __forceinline__ ull add2(ull a, ull b) {
    ull r; asm("add.rn.f32x2 %0, %1, %2;" : "=l"(r) : "l"(a), "l"(b)); return r;
}
__device__ __forceinline__ void unpack2(ull v, float& lo, float& hi) {
    asm("mov.b64 {%0, %1}, %2;" : "=f"(lo), "=f"(hi) : "l"(v));
}
__device__ __forceinline__ void cp_async16(uint32_t dst, const float* src) {
    asm volatile("cp.async.cg.shared.global [%0], [%1], 16;" :: "r"(dst), "l"(src));
}
__device__ __forceinline__ void mbar_init(uint32_t a, uint32_t cnt) {
    asm volatile("mbarrier.init.shared.b64 [%0], %1;" :: "r"(a), "r"(cnt) : "memory");
}
__device__ __forceinline__ void mbar_arrive(uint32_t a) {
    asm volatile("mbarrier.arrive.release.cta.shared::cta.b64 _, [%0];" :: "r"(a) : "memory");
}
__device__ __forceinline__ void cpasync_mbar_arrive_noinc(uint32_t a) {
    asm volatile("cp.async.mbarrier.arrive.noinc.shared::cta.b64 [%0];" :: "r"(a) : "memory");
}
__device__ __forceinline__ void mbar_wait(uint32_t a, uint32_t parity) {
    asm volatile(
        "{\n\t.reg .pred P;\n\t"
        "WL_%=:\n\t"
        "mbarrier.try_wait.parity.acquire.cta.shared::cta.b64 P, [%0], %1, 0x989680;\n\t"
        "@P bra.uni WD_%=;\n\t"
        "bra.uni WL_%=;\n\t"
        "WD_%=:\n\t}"
        :: "r"(a), "r"(parity) : "memory");
}

// ---- pre-pass: x [16][8192] -> g_xT [8192][16]
__global__ void __launch_bounds__(256, 1)
transpose_x_kernel(const float* __restrict__ x)
{
    const int col = blockIdx.x * 256 + threadIdx.x;
    float v[B_SZ];
#pragma unroll
    for (int b = 0; b < B_SZ; b++) v[b] = __ldg(x + (size_t)b * IN_F + col);
    float4* dst = reinterpret_cast<float4*>(g_xT + (size_t)col * B_SZ);
#pragma unroll
    for (int q = 0; q < 4; q++)
        dst[q] = make_float4(v[4*q], v[4*q+1], v[4*q+2], v[4*q+3]);
}

__global__ void __launch_bounds__(THREADS, 1)
axcore_linear_kernel(const float* __restrict__ W,
                     const float* __restrict__ scale,
                     const float* __restrict__ bias,
                     float* __restrict__ out)
{
    extern __shared__ char smem[];
    float* ws = reinterpret_cast<float*>(smem + WS_OFF);
    float* xr = reinterpret_cast<float*>(smem + XR_OFF);
    float* sc = reinterpret_cast<float*>(smem + SC_OFF);
    const uint32_t smem_u32 = (uint32_t)__cvta_generic_to_shared(smem);
#define FULLW(s)  (smem_u32 + (s) * 8)        // cnt 64, noinc
#define EMPTYW(s) (smem_u32 + 64 + (s) * 8)   // cnt 16, elected
#define FULLX(s)  (smem_u32 + 128 + (s) * 8)  // cnt 64, noinc

    const int tid  = threadIdx.x;
    const int lane = tid & 31;
    const int warp = tid >> 5;
    const int row0 = blockIdx.x * RPB;
    const float* Wb = W + (size_t)row0 * IN_F;
    const bool prod = (warp >= 16);       // warps 16,17 pure producers
    const int ptid  = tid - 512;          // 0..63 for producers

    if (tid == 0) {
#pragma unroll
        for (int s = 0; s < WST; s++) {
            mbar_init(FULLW(s), 64);
            mbar_init(EMPTYW(s), 16);
        }
#pragma unroll
        for (int s = 0; s < XST; s++) mbar_init(FULLX(s), 64);
    }
    __syncthreads();

    // ---- W group gi -> ring slot (64 producer threads, 32x cp16 each)
#define ISSUE_W(gi, slot) do {                                                \
        const float* _s = Wb + (size_t)(gi) * GRP;                            \
        const uint32_t _d = smem_u32 + WS_OFF + (slot) * (WS_STAGE_F * 4);    \
        _Pragma("unroll")                                                     \
        for (int j = 0; j < 32; j++) {                                        \
            const int i = ptid + 64 * j;        /* 0..2047 */                 \
            const int r = i >> 5, cf = i & 31;  /* 64 rows x 32 x 16B */      \
            cp_async16(_d + (uint32_t)(r * GRP + cf * 4) * 4,                 \
                       _s + (size_t)r * IN_F + cf * 4);                       \
        }                                                                     \
        cpasync_mbar_arrive_noinc(FULLW(slot));                               \
    } while (0)

    // ---- x chunk cn -> [col][XPAD] stage via cp.async from g_xT
#define ISSUE_X(cn, slot) do {                                                \
        const float* _s = g_xT + (size_t)(cn) * XCH * B_SZ;                   \
        const uint32_t _d = smem_u32 + XR_OFF + (slot) * (XR_STAGE_F * 4);    \
        _Pragma("unroll")                                                     \
        for (int j = 0; j < 16; j++) {                                        \
            const int i = ptid + 64 * j;         /* 0..1023 */                \
            const int cl = i >> 2, q = i & 3;    /* 256 cols x 4 x 16B */     \
            cp_async16(_d + (uint32_t)(cl * XPAD + q * 4) * 4,                \
                       _s + cl * B_SZ + q * 4);                               \
        }                                                                     \
        cpasync_mbar_arrive_noinc(FULLX(slot));                               \
    } while (0)

    // ---- prologue: W groups 0..2, x chunks 0,1; stage scales
    if (prod) {
        ISSUE_W(0, 0); ISSUE_W(1, 1); ISSUE_W(2, 2);
        ISSUE_X(0, 0); ISSUE_X(1, 1);
    }
    for (int i = tid; i < RPB * NGRP; i += THREADS)
        sc[i] = scale[(size_t)row0 * NGRP + i];
    __syncthreads();   // sc visible

    if (prod) {
        // ---- producer loop: W three ahead, x chunks at odd g
        for (int g = 0; g < NGRP; g++) {
            if (g + 3 < NGRP) {
                const int s = (g + 3) & 3;
                mbar_wait(EMPTYW(s), ((((g + 3) >> 2)) & 1) ^ 1);
                ISSUE_W(g + 3, s);
                // EMPTYW drained => consumers finished g-1 => chunk
                // ((g-1)>>1)-1+1... : chunk cn-3 fully read => slot cn%3 free.
                if (g & 1) {
                    const int cn = (g + 3) >> 1;
                    if (cn < NXCH) ISSUE_X(cn, cn % 3);
                }
            }
        }
        return;   // producers exit; no further block-wide sync needed
    }

    // ---- consumers: warps 0..15
    const int half = warp >> 3;          // batch half
    const int wr0  = (warp & 7) * 8;     // warp's first row in block

    ull acc[8][4];
#pragma unroll
    for (int r = 0; r < 8; r++)
#pragma unroll
        for (int q = 0; q < 4; q++) acc[r][q] = 0ull;

    for (int g = 0; g < NGRP; g++) {
        mbar_wait(FULLW(g & 3), (g >> 2) & 1);
        if (!(g & 1)) {
            const int cn = g >> 1;
            mbar_wait(FULLX(cn % 3), (cn / 3) & 1);
        }

        const float* wst = ws + (g & 3) * WS_STAGE_F + wr0 * GRP;
        const int cn = g >> 1;
        const float* xb = xr + (cn % 3) * XR_STAGE_F
                          + ((g & 1) * GRP) * XPAD + half * 8;
        float s[8];
#pragma unroll
        for (int r = 0; r < 8; r++) s[r] = sc[(wr0 + r) * NGRP + g];

#pragma unroll
        for (int k = 0; k < 4; k++) {
            const int kc = lane + 32 * k;           // col within group
            const float* xp = xb + kc * XPAD;
            ulonglong2 va = *reinterpret_cast<const ulonglong2*>(xp);
            ulonglong2 vb = *reinterpret_cast<const ulonglong2*>(xp + 4);
            ull x2[4] = { va.x, va.y, vb.x, vb.y };
#pragma unroll
            for (int r = 0; r < 8; r++) {
                const ull w2 = pack2(wst[r * GRP + kc] * s[r]);
#pragma unroll
                for (int q = 0; q < 4; q++) fma2(acc[r][q], w2, x2[q]);
            }
        }

        if (lane == 0) mbar_arrive(EMPTYW(g & 3));
    }

    // ---- butterfly reduction across lanes
#pragma unroll
    for (int r = 0; r < 8; r++)
#pragma unroll
        for (int q = 0; q < 4; q++) {
            ull v = acc[r][q];
#pragma unroll
            for (int off = 16; off > 0; off >>= 1)
                v = add2(v, __shfl_xor_sync(0xffffffffu, v, off));
            acc[r][q] = v;
        }

    // ---- writeback: lane (r*4+q) -> row wr0+r, batches (half*8+2q, +1)
#pragma unroll
    for (int r = 0; r < 8; r++)
#pragma unroll
        for (int q = 0; q < 4; q++)
            if (lane == r * 4 + q) {
                const int row = row0 + wr0 + r;
                const int b0  = half * 8 + 2 * q;
                const float bv = __ldg(bias + row);
                float lo, hi;
                unpack2(acc[r][q], lo, hi);
                out[(size_t)b0 * OUT_F + row]       = lo + bv;
                out[(size_t)(b0 + 1) * OUT_F + row] = hi + bv;
            }
}

extern "C" void kernel_launch(void* const* d_in, const int* in_sizes, int n_in,
                              void* d_out, int out_size)
{
    const float* x     = (const float*)d_in[0]; // [16, 8192]
    const float* W     = (const float*)d_in[1]; // [8192, 8192]
    const float* scale = (const float*)d_in[2]; // [8192, 64]
    const float* bias  = (const float*)d_in[3]; // [1, 8192]
    // d_in[4] = types — constant lookup in reference; no float math: unused
    float* out = (float*)d_out;                 // [16, 8192]

    cudaFuncSetAttribute(axcore_linear_kernel,
                         cudaFuncAttributeMaxDynamicSharedMemorySize, SMEM_TOTAL);

    transpose_x_kernel<<<IN_F / 256, 256>>>(x);
    axcore_linear_kernel<<<OUT_F / RPB, THREADS, SMEM_TOTAL>>>(W, scale, bias, out);
}